// round 6
// baseline (speedup 1.0000x reference)
#include <cuda_runtime.h>
#include <cstdint>

// Reference math reduces to an all-zero output:
//   probs = one-hot at basis-state 0; gather indices 1<<q never hit index 0
//   -> projected features are exactly 0 -> p1 @ p2^T == 0.
// Kernel = pure 256 MB zero-fill of d_out (float32 8192x8192). HBM-write-bound.
//
// History (kernel / total):
//   R1: 1 store/thr 65536x256            -> 36.9 / 39.4us (7.27 TB/s)
//   R2: 16-deep grid-stride + __stcs     -> 38.8 / 42.1us
//   R3: stride-2 lanes (de-coalesced)    -> 52.6 / 54.5us
//   R4: 2 contig stores 32768x256        -> 36.5 / 39.7us
//   R5: 2 contig stores 16384x512        -> 36.5 / 40.2us
// All coalesced STG variants sit at the ~7.0-7.3 TB/s HBM write ceiling.
// R6: probe the driver memset path — cudaMemsetAsync captures as a native
// graph memset node (legal: no alloc, no sync; legacy stream is captured,
// as proven by prior <<<>>> launches capturing fine). 0x00 fill == 0.0f.

extern "C" void kernel_launch(void* const* d_in, const int* in_sizes, int n_in,
                              void* d_out, int out_size) {
    (void)d_in; (void)in_sizes; (void)n_in;
    cudaMemsetAsync(d_out, 0, (size_t)out_size * sizeof(float), 0);
}

// round 7
// speedup vs baseline: 1.0412x; 1.0412x over previous
#include <cuda_runtime.h>
#include <cstdint>

// FINAL — converged at the HBM write roofline.
//
// Reference math reduces to an all-zero output:
//   _encode always yields |0...0> -> probs is one-hot at index 0; the gather
//   indices 1<<q (q=0..7) never hit index 0 -> projected features are exactly
//   0 -> normalized 0 -> p1 @ p2^T == 0 (8192x8192 f32, 256 MB).
// The kernel is therefore a pure zero-fill of d_out; the optimum is the HBM
// write ceiling.
//
// Sweep results (kernel / total):
//   R1: 1 store/thr, 65536x256             36.9 / 39.4us  (7.27 TB/s)
//   R2: 16-deep grid-stride + __stcs       38.8 / 42.1us  (regression)
//   R3: stride-2 lanes (de-coalesced)      52.6 / 54.5us  (regression)
//   R4: 2 contig stores/thr, 32768x256     36.5 / 39.7us  <- best kernel
//   R5: 2 contig stores/thr, 16384x512     36.5 / 40.2us  (tie)
//   R6: graph memset node                   --  / 41.3us  (no advantage)
// All coalesced STG.128 variants saturate at ~7.3 TB/s effective; remaining
// dur variation is harness replay noise. This is the R4 configuration.

__global__ void zero_fill2c(float4* __restrict__ out) {
    size_t base = (size_t)blockIdx.x * (blockDim.x * 2);
    size_t i = base + threadIdx.x;
    const float4 z = make_float4(0.0f, 0.0f, 0.0f, 0.0f);
    out[i] = z;                  // STG.128, 32 consecutive lanes
    out[i + blockDim.x] = z;     // STG.128, next contiguous 4 KB chunk
}

__global__ void zero_fill_generic(float* __restrict__ out, size_t n) {
    size_t stride = (size_t)gridDim.x * blockDim.x;
    for (size_t i = (size_t)blockIdx.x * blockDim.x + threadIdx.x; i < n;
         i += stride)
        out[i] = 0.0f;
}

extern "C" void kernel_launch(void* const* d_in, const int* in_sizes, int n_in,
                              void* d_out, int out_size) {
    (void)d_in; (void)in_sizes; (void)n_in;

    float* out = (float*)d_out;
    size_t n  = (size_t)out_size;   // 67,108,864 floats
    size_t n4 = n / 4;              // 16,777,216 float4

    const int threads = 256;
    const size_t per_block = (size_t)threads * 2;   // 512 float4 per block

    if ((n % 4 == 0) && (n4 % per_block == 0)) {
        unsigned blocks = (unsigned)(n4 / per_block);   // 32768
        zero_fill2c<<<blocks, threads>>>((float4*)out);
    } else {
        unsigned blocks = 8192;
        zero_fill_generic<<<blocks, 512>>>(out, n);
    }
}

// round 8
// speedup vs baseline: 1.0479x; 1.0065x over previous
#include <cuda_runtime.h>
#include <cstdint>

// Converged at the HBM write roofline.
//
// Reference math reduces to an all-zero output:
//   _encode always yields |0...0> -> probs one-hot at index 0; gather indices
//   1<<q never hit 0 -> projected features exactly 0 -> p1 @ p2^T == 0
//   (8192x8192 f32, 256 MB). Kernel = pure zero-fill of d_out.
//
// Sweep (kernel / total us):
//   R1: 1 store/thr 65536x256              36.9 / 39.4
//   R2: 16-deep grid-stride + __stcs       38.8 / 42.1  (regression)
//   R3: stride-2 lanes (de-coalesced)      52.6 / 54.5  (regression)
//   R4: 2 contig stores 32768x256          36.5 / 39.7
//   R5: 2 contig stores 16384x512          36.5 / 40.2
//   R6: graph memset node                   --  / 41.3
//   R7: R4 re-run                          37.4 / 39.6  (noise ±0.9us)
// R8: 4 block-contiguous stores/thread, compile-time block size so ptxas
// folds +4KB/+8KB/+12KB into STG immediates (one base reg, 4 STG.128).

constexpr int kThreads = 256;
constexpr int kStoresPerThread = 4;

__global__ void __launch_bounds__(kThreads)
zero_fill4c(float4* __restrict__ out) {
    size_t base = (size_t)blockIdx.x * (kThreads * kStoresPerThread)
                + threadIdx.x;
    const float4 z = make_float4(0.0f, 0.0f, 0.0f, 0.0f);
#pragma unroll
    for (int k = 0; k < kStoresPerThread; ++k)
        out[base + (size_t)k * kThreads] = z;   // imm-offset STG.128, coalesced
}

__global__ void zero_fill_generic(float* __restrict__ out, size_t n) {
    size_t stride = (size_t)gridDim.x * blockDim.x;
    for (size_t i = (size_t)blockIdx.x * blockDim.x + threadIdx.x; i < n;
         i += stride)
        out[i] = 0.0f;
}

extern "C" void kernel_launch(void* const* d_in, const int* in_sizes, int n_in,
                              void* d_out, int out_size) {
    (void)d_in; (void)in_sizes; (void)n_in;

    float* out = (float*)d_out;
    size_t n  = (size_t)out_size;   // 67,108,864 floats
    size_t n4 = n / 4;              // 16,777,216 float4

    const size_t per_block = (size_t)kThreads * kStoresPerThread;  // 1024

    if ((n % 4 == 0) && (n4 % per_block == 0)) {
        unsigned blocks = (unsigned)(n4 / per_block);   // 16384
        zero_fill4c<<<blocks, kThreads>>>((float4*)out);
    } else {
        zero_fill_generic<<<8192, 512>>>(out, n);
    }
}